// round 2
// baseline (speedup 1.0000x reference)
#include <cuda_runtime.h>
#include <math.h>

#define N_NODES 50000
#define KNBR    12
#define DFEAT   64
#define EFEAT   64
#define CFEAT   192
#define HA      64
#define NEDGE   (N_NODES*KNBR)
#define EPSV    1e-5f
#define CST     196   // padded c-tile stride (bank-conflict avoidance)

// ---------------- device scratch (allocation-free rule: device globals) ----
__device__ float  g_elin[NEDGE*64];     // e_lin, later reused for p
__device__ float  g_pooled[N_NODES*64];
__device__ float  g_lens[N_NODES];
__device__ double g_sumE[64], g_ssqE[64];
__device__ double g_sumP[64], g_ssqP[64];
__device__ double g_sumO[64], g_ssqO[64];
__device__ double g_cnt;
__device__ float  g_coefs[384];  // [0:64) scaleE [64:128) shiftE [128..) scaleP shiftP scaleO shiftO

__device__ __forceinline__ float softplusf(float x) {
    float ax = fabsf(x);
    float r  = log1pf(expf(-ax));
    return x > 0.f ? x + r : r;
}

// ---------------- K_zero: clear accumulators (runs every replay) -----------
__global__ void k_zero() {
    int t = threadIdx.x;
    if (t < 64) {
        g_sumE[t] = 0.0; g_ssqE[t] = 0.0;
        g_sumP[t] = 0.0; g_ssqP[t] = 0.0;
        g_sumO[t] = 0.0; g_ssqO[t] = 0.0;
    }
    if (t == 64) g_cnt = 0.0;
}

// ---------------- K_lens: per-node mask length + global count --------------
__global__ void k_lens(const float* __restrict__ nmask) {
    int n = blockIdx.x * 256 + threadIdx.x;
    float eff = 0.f;
    if (n < N_NODES) {
        float L = 0.f;
#pragma unroll
        for (int k = 0; k < KNBR; k++) L += nmask[n*KNBR + k];
        g_lens[n] = L;
        eff = (L > 0.f) ? L : 1.0f;
    }
    __shared__ float red[256];
    red[threadIdx.x] = eff;
    __syncthreads();
    for (int s = 128; s > 0; s >>= 1) {
        if (threadIdx.x < s) red[threadIdx.x] += red[threadIdx.x + s];
        __syncthreads();
    }
    if (threadIdx.x == 0) atomicAdd(&g_cnt, (double)red[0]);
}

// ---------------- K1: e_lin = c1 @ W_edge + b, masked stats -----------------
// block: 256 threads, 64 edges. thread = (eg:16 groups of 4 edges) x (jg:16 of 4 cols)
__global__ __launch_bounds__(256) void k1_edge(
    const float* __restrict__ nodef, const float* __restrict__ edgef,
    const int* __restrict__ nbr, const float* __restrict__ nmask,
    const float* __restrict__ W, const float* __restrict__ bE)
{
    extern __shared__ float smem[];
    float* sW   = smem;               // 192*64
    float* sC   = sW + 192*64;        // 64*CST
    float* sM   = sC + 64*CST;        // 64
    float* sSum = sM + 64;            // 64
    float* sSsq = sSum + 64;          // 64

    int t = threadIdx.x;
    int eb = blockIdx.x * 64;

    const float4* W4 = (const float4*)W;
    float4* sW4 = (float4*)sW;
    for (int i = t; i < 192*16; i += 256) sW4[i] = W4[i];

    for (int i = t; i < 64*192; i += 256) {
        int le = i / 192, c = i % 192;
        int e  = eb + le;
        int n  = e / KNBR;
        float v;
        if (c < 64)       v = nodef[n*64 + c];
        else if (c < 128) v = nodef[nbr[e]*64 + (c - 64)];
        else              v = edgef[e*64 + (c - 128)];
        sC[le*CST + c] = v;
    }
    if (t < 64) {
        int e = eb + t;
        int n = e / KNBR, k = e % KNBR;
        float L = g_lens[n];
        sM[t] = (L > 0.f) ? nmask[e] : (k == 0 ? 1.f : 0.f);
        sSum[t] = 0.f; sSsq[t] = 0.f;
    }
    __syncthreads();

    int jg = t & 15, eg = t >> 4;
    int j0 = jg * 4, e0 = eg * 4;
    float acc[4][4];
#pragma unroll
    for (int a = 0; a < 4; a++)
#pragma unroll
        for (int b = 0; b < 4; b++) acc[a][b] = 0.f;

#pragma unroll 4
    for (int c = 0; c < 192; c++) {
        float4 w = *(const float4*)&sW[c*64 + j0];
#pragma unroll
        for (int ee = 0; ee < 4; ee++) {
            float cv = sC[(e0+ee)*CST + c];
            acc[ee][0] = fmaf(cv, w.x, acc[ee][0]);
            acc[ee][1] = fmaf(cv, w.y, acc[ee][1]);
            acc[ee][2] = fmaf(cv, w.z, acc[ee][2]);
            acc[ee][3] = fmaf(cv, w.w, acc[ee][3]);
        }
    }

    float4 bj = *(const float4*)&bE[j0];
    float psum[4] = {0,0,0,0}, pssq[4] = {0,0,0,0};
#pragma unroll
    for (int ee = 0; ee < 4; ee++) {
        int e = eb + e0 + ee;
        float m = sM[e0 + ee];
        float4 o;
        o.x = acc[ee][0] + bj.x; o.y = acc[ee][1] + bj.y;
        o.z = acc[ee][2] + bj.z; o.w = acc[ee][3] + bj.w;
        *(float4*)&g_elin[e*64 + j0] = o;
        psum[0] += o.x*m; pssq[0] += o.x*o.x*m;
        psum[1] += o.y*m; pssq[1] += o.y*o.y*m;
        psum[2] += o.z*m; pssq[2] += o.z*o.z*m;
        psum[3] += o.w*m; pssq[3] += o.w*o.w*m;
    }
#pragma unroll
    for (int jj = 0; jj < 4; jj++) {
        atomicAdd(&sSum[j0+jj], psum[jj]);
        atomicAdd(&sSsq[j0+jj], pssq[jj]);
    }
    __syncthreads();
    if (t < 64) {
        atomicAdd(&g_sumE[t], (double)sSum[t]);
        atomicAdd(&g_ssqE[t], (double)sSsq[t]);
    }
}

// ---------------- K_fin: BN stats -> scale/shift ---------------------------
__global__ void k_finalize(const float* __restrict__ gamma,
                           const float* __restrict__ beta, int which)
{
    int j = threadIdx.x;
    if (j >= 64) return;
    double cnt = (which == 2) ? (double)N_NODES : g_cnt;
    double s, q;
    if (which == 0)      { s = g_sumE[j]; q = g_ssqE[j]; }
    else if (which == 1) { s = g_sumP[j]; q = g_ssqP[j]; }
    else                 { s = g_sumO[j]; q = g_ssqO[j]; }
    double mean = s / cnt;
    double var  = q / cnt - mean * mean;
    float inv   = (float)(1.0 / sqrt(var + (double)EPSV));
    float sc    = gamma[j] * inv;
    g_coefs[which*128 + j]      = sc;
    g_coefs[which*128 + 64 + j] = beta[j] - (float)mean * sc;
}

// ---------------- K3: fused edge-update + attention + value ----------------
// block: 256 threads, 4 nodes (48 edges).
__global__ __launch_bounds__(256) void k3_att(
    const float* __restrict__ nodef, const float* __restrict__ edgef,
    const int* __restrict__ nbr, const float* __restrict__ nmask,
    const float* __restrict__ W1, const float* __restrict__ b1,
    const float* __restrict__ W2, const float* __restrict__ b2,
    const float* __restrict__ Wv, const float* __restrict__ bv,
    float* __restrict__ out_edges)
{
    extern __shared__ float smem[];
    float* sW    = smem;               // 192*128
    float* sC    = sW + 192*128;       // 48*CST
    float* sV    = sC + 48*CST;        // 48*64
    float* sCoef = sV + 48*64;         // 128
    float* sB1   = sCoef + 128;        // 64
    float* sBV   = sB1 + 64;           // 64
    float* sW2   = sBV + 64;           // 64
    float* sLog  = sW2 + 64;           // 48*4
    float* sAtt  = sLog + 192;         // 48*4
    float* sM    = sAtt + 192;         // 48
    float* sSum  = sM + 48;            // 64
    float* sSsq  = sSum + 64;          // 64

    int t  = threadIdx.x;
    int n0 = blockIdx.x * 4;
    int eb = n0 * KNBR;

    // weights into smem: sW[c*128 + (h*16+a)] = W1, cols 64.. = Wv
    for (int i = t; i < 4*192*16; i += 256) {
        int h = i / 3072, r = i % 3072, c = r / 16, a = r % 16;
        sW[c*128 + h*16 + a] = W1[i];
    }
    for (int i = t; i < 4*192*16; i += 256) {
        int h = i / 3072, r = i % 3072, c = r / 16, a = r % 16;
        sW[c*128 + 64 + h*16 + a] = Wv[i];
    }
    if (t < 128) sCoef[t] = g_coefs[t];
    if (t < 64)  { sB1[t] = b1[t]; sBV[t] = bv[t]; sW2[t] = W2[t];
                   sSum[t] = 0.f; sSsq[t] = 0.f; }
    if (t < 48) {
        int e = eb + t;
        int n = n0 + t / KNBR, k = t % KNBR;
        float L = g_lens[n];
        sM[t] = (L > 0.f) ? nmask[e] : (k == 0 ? 1.f : 0.f);
    }
    if (t < 192) sLog[t] = 0.f;
    __syncthreads();

    // phase 1a: pair part of c2
    for (int i = t; i < 48*128; i += 256) {
        int le = i / 128, c = i % 128;
        int e  = eb + le;
        int n  = n0 + le / KNBR;
        float v = (c < 64) ? nodef[n*64 + c] : nodef[nbr[e]*64 + (c - 64)];
        sC[le*CST + c] = v;
    }
    // phase 1b: edge_updated
    for (int i = t; i < 48*64; i += 256) {
        int le = i / 64, j = i % 64;
        int e  = eb + le;
        float m  = sM[le];
        float el = g_elin[e*64 + j];
        float ef = edgef[e*64 + j];
        float eu = softplusf(ef + (el * sCoef[j] + sCoef[64 + j]) * m);
        out_edges[e*64 + j] = eu;
        sC[le*CST + 128 + j] = eu;
    }
    __syncthreads();

    // phase 2: fused GEMV  (48 edges x 128 outputs)
    int jg = t & 31, eg = t >> 5;
    int j0 = jg * 4, e0 = eg * 6;
    float acc[6][4];
#pragma unroll
    for (int a = 0; a < 6; a++)
#pragma unroll
        for (int b = 0; b < 4; b++) acc[a][b] = 0.f;

#pragma unroll 2
    for (int c = 0; c < 192; c++) {
        float4 w = *(const float4*)&sW[c*128 + j0];
#pragma unroll
        for (int ee = 0; ee < 6; ee++) {
            float cv = sC[(e0+ee)*CST + c];
            acc[ee][0] = fmaf(cv, w.x, acc[ee][0]);
            acc[ee][1] = fmaf(cv, w.y, acc[ee][1]);
            acc[ee][2] = fmaf(cv, w.z, acc[ee][2]);
            acc[ee][3] = fmaf(cv, w.w, acc[ee][3]);
        }
    }

    if (j0 < 64) {  // attention path: softplus + W_att2 contraction
        int h = j0 >> 4;
        float bx = sB1[j0], by = sB1[j0+1], bz = sB1[j0+2], bw = sB1[j0+3];
        float wx = sW2[j0], wy = sW2[j0+1], wz = sW2[j0+2], ww = sW2[j0+3];
#pragma unroll
        for (int ee = 0; ee < 6; ee++) {
            int le = e0 + ee;
            float lp = softplusf(acc[ee][0] + bx) * wx
                     + softplusf(acc[ee][1] + by) * wy
                     + softplusf(acc[ee][2] + bz) * wz
                     + softplusf(acc[ee][3] + bw) * ww;
            atomicAdd(&sLog[le*4 + h], lp);
        }
    } else {        // value path
        int jv = j0 - 64;
        float bx = sBV[jv], by = sBV[jv+1], bz = sBV[jv+2], bw = sBV[jv+3];
#pragma unroll
        for (int ee = 0; ee < 6; ee++) {
            int le = e0 + ee;
            sV[le*64 + jv]     = acc[ee][0] + bx;
            sV[le*64 + jv + 1] = acc[ee][1] + by;
            sV[le*64 + jv + 2] = acc[ee][2] + bz;
            sV[le*64 + jv + 3] = acc[ee][3] + bw;
        }
    }
    __syncthreads();

    // phase 3: masked softmax over k, per (node, head)
    if (t < 16) {
        int ln = t / 4, h = t % 4;
        float bb = b2[h];
        float mx = -1e30f;
#pragma unroll
        for (int k = 0; k < KNBR; k++) {
            int le = ln*KNBR + k;
            if (sM[le] > 0.f) {
                float l = sLog[le*4 + h] + bb;
                mx = fmaxf(mx, l);
            }
        }
        float ex[KNBR]; float ssum = 0.f;
#pragma unroll
        for (int k = 0; k < KNBR; k++) {
            int le = ln*KNBR + k;
            float v = (sM[le] > 0.f) ? expf(sLog[le*4 + h] + bb - mx) : 0.f;
            ex[k] = v; ssum += v;
        }
        float inv = 1.f / ssum;
#pragma unroll
        for (int k = 0; k < KNBR; k++) sAtt[(ln*KNBR + k)*4 + h] = ex[k] * inv;
    }
    __syncthreads();

    // phase 4: p = att * v, store (reuse g_elin), masked stats
    for (int i = t; i < 48*64; i += 256) {
        int le = i / 64, j = i % 64, h = j >> 4;
        int e  = eb + le;
        float p = sAtt[le*4 + h] * sV[le*64 + j];
        g_elin[e*64 + j] = p;
        float m = sM[le];
        atomicAdd(&sSum[j], p * m);
        atomicAdd(&sSsq[j], p * p * m);
    }
    __syncthreads();
    if (t < 64) {
        atomicAdd(&g_sumP[t], (double)sSum[t]);
        atomicAdd(&g_ssqP[t], (double)sSsq[t]);
    }
}

// ---------------- K5: head_feats + pooled + out-BN stats -------------------
// block: 256 threads = 64 channels x 4 node lanes; 64 nodes per block
__global__ __launch_bounds__(256) void k5_pool(const float* __restrict__ nmask)
{
    int t = threadIdx.x;
    int j = t & 63, nl = t >> 6;
    int n0 = blockIdx.x * 64;
    float scP = g_coefs[128 + j], shP = g_coefs[192 + j];
    float psum = 0.f, pssq = 0.f;
    for (int i = 0; i < 16; i++) {
        int n = n0 + nl * 16 + i;
        if (n >= N_NODES) break;
        float L = g_lens[n];
        float pooled = 0.f;
#pragma unroll
        for (int k = 0; k < KNBR; k++) {
            float m = (L > 0.f) ? nmask[n*KNBR + k] : (k == 0 ? 1.f : 0.f);
            float p = g_elin[(n*KNBR + k)*64 + j];
            pooled += softplusf(p * scP + shP) * m;
        }
        g_pooled[n*64 + j] = pooled;
        psum += pooled; pssq += pooled * pooled;
    }
    __shared__ float red[256], red2[256];
    red[t] = psum; red2[t] = pssq;
    __syncthreads();
    if (nl == 0) {
        float s = red[j] + red[64+j] + red[128+j] + red[192+j];
        float q = red2[j] + red2[64+j] + red2[128+j] + red2[192+j];
        atomicAdd(&g_sumO[j], (double)s);
        atomicAdd(&g_ssqO[j], (double)q);
    }
}

// ---------------- K7: residual + out BN -------------------------------------
__global__ void k7_out(const float* __restrict__ nodef, float* __restrict__ out_nodes)
{
    int i = blockIdx.x * 256 + threadIdx.x;
    if (i < N_NODES*64) {
        int j = i & 63;
        out_nodes[i] = nodef[i] + g_coefs[256 + j] * g_pooled[i] + g_coefs[320 + j];
    }
}

// ---------------- launch -----------------------------------------------------
extern "C" void kernel_launch(void* const* d_in, const int* in_sizes, int n_in,
                              void* d_out, int out_size)
{
    const float* nodef = (const float*)d_in[0];
    const float* edgef = (const float*)d_in[1];
    const int*   nbr   = (const int*)d_in[2];
    const float* nmask = (const float*)d_in[3];
    const float* W_edge = (const float*)d_in[4];
    const float* b_edge = (const float*)d_in[5];
    const float* g_ebn  = (const float*)d_in[6];
    const float* b_ebn  = (const float*)d_in[7];
    const float* W1     = (const float*)d_in[8];
    const float* b1     = (const float*)d_in[9];
    const float* W2     = (const float*)d_in[10];
    const float* b2     = (const float*)d_in[11];
    const float* Wv     = (const float*)d_in[12];
    const float* bv     = (const float*)d_in[13];
    const float* g_abn  = (const float*)d_in[14];
    const float* b_abn  = (const float*)d_in[15];
    const float* g_obn  = (const float*)d_in[16];
    const float* b_obn  = (const float*)d_in[17];

    float* out_nodes = (float*)d_out;
    float* out_edges = out_nodes + (size_t)N_NODES * 64;

    const int smem1 = (192*64 + 64*CST + 64 + 64 + 64) * 4;
    const int smem3 = (192*128 + 48*CST + 48*64 + 128 + 64 + 64 + 64
                       + 192 + 192 + 48 + 64 + 64) * 4;
    cudaFuncSetAttribute(k1_edge, cudaFuncAttributeMaxDynamicSharedMemorySize, smem1);
    cudaFuncSetAttribute(k3_att,  cudaFuncAttributeMaxDynamicSharedMemorySize, smem3);

    k_zero<<<1, 128>>>();
    k_lens<<<(N_NODES + 255) / 256, 256>>>(nmask);
    k1_edge<<<NEDGE / 64, 256, smem1>>>(nodef, edgef, nbr, nmask, W_edge, b_edge);
    k_finalize<<<1, 64>>>(g_ebn, b_ebn, 0);
    k3_att<<<N_NODES / 4, 256, smem3>>>(nodef, edgef, nbr, nmask,
                                        W1, b1, W2, b2, Wv, bv, out_edges);
    k_finalize<<<1, 64>>>(g_abn, b_abn, 1);
    k5_pool<<<(N_NODES + 63) / 64, 256>>>(nmask);
    k_finalize<<<1, 64>>>(g_obn, b_obn, 2);
    k7_out<<<(N_NODES*64 + 255) / 256, 256>>>(nodef, out_nodes);
}

// round 3
// speedup vs baseline: 2.2168x; 2.2168x over previous
#include <cuda_runtime.h>
#include <math.h>

#define N_NODES 50000
#define KNBR    12
#define NEDGE   (N_NODES*KNBR)
#define EPSV    1e-5f
#define CST     196
#define NSM     152

typedef unsigned long long ull;

// ---------------- device scratch ----------------
__device__ float  g_elin[NEDGE*64];     // e_lin, later reused for p
__device__ float  g_pooled[N_NODES*64];
__device__ float  g_lens[N_NODES];
__device__ double g_sumE[64], g_ssqE[64];
__device__ double g_sumP[64], g_ssqP[64];
__device__ double g_sumO[64], g_ssqO[64];
__device__ double g_cnt;
__device__ float  g_coefs[384];
__device__ unsigned int g_t1, g_t3;

// ---------------- f32x2 helpers ----------------
__device__ __forceinline__ ull pack2(float x, float y) {
    ull r; asm("mov.b64 %0,{%1,%2};" : "=l"(r) : "f"(x), "f"(y)); return r;
}
__device__ __forceinline__ void ffma2(ull& d, ull a, ull b) {
    asm("fma.rn.f32x2 %0,%1,%2,%0;" : "+l"(d) : "l"(a), "l"(b));
}
__device__ __forceinline__ float2 unpack2(ull v) {
    float2 r; asm("mov.b64 {%0,%1},%2;" : "=f"(r.x), "=f"(r.y) : "l"(v)); return r;
}

// ---------------- fast softplus: no MUFU, fma/alu only ----------------
__device__ __forceinline__ float fsp(float x) {
    float t  = fmaxf(-fabsf(x) * 1.4426950409f, -126.f);
    float kf = (t + 12582912.f) - 12582912.f;      // round-to-nearest int
    float f  = t - kf;                              // [-0.5, 0.5]
    float p  = 1.f + f*(0.6931471806f + f*(0.2402265070f
             + f*(0.0555041087f + f*0.0096181291f)));
    float z  = p * __int_as_float(((int)kf + 127) << 23);  // exp(-|x|) in (0,1]
    float w  = 1.f + z;
    float y1 = w - 1.f;                             // exact (Sterbenz)
    float dz = z - y1;                              // rounding residual
    int   wi = __float_as_int(w);
    float e  = (float)((wi >> 23) - 127);
    float m  = __int_as_float((wi & 0x7FFFFF) | 0x3F800000);
    if (m > 1.41421356f) { m *= 0.5f; e += 1.f; }
    float y  = m - 1.f;                             // [-0.293, 0.4143]
    float r  = y*(1.f + y*(-0.5f + y*(0.33333333f + y*(-0.25f + y*(0.2f
             + y*(-0.16666667f + y*(0.14285714f + y*(-0.125f
             + y*0.11111111f))))))));
    float lnw = e * 0.6931471806f + r + dz * (1.f - y1);
    return fmaxf(x, 0.f) + lnw;
}

// ---------------- K_zero ----------------
__global__ void k_zero() {
    int t = threadIdx.x;
    if (t < 64) {
        g_sumE[t] = 0.0; g_ssqE[t] = 0.0;
        g_sumP[t] = 0.0; g_ssqP[t] = 0.0;
        g_sumO[t] = 0.0; g_ssqO[t] = 0.0;
    }
    if (t == 64) g_cnt = 0.0;
    if (t == 65) g_t1 = 0u;
    if (t == 66) g_t3 = 0u;
}

// ---------------- K_lens ----------------
__global__ void k_lens(const float* __restrict__ nmask) {
    int n = blockIdx.x * 256 + threadIdx.x;
    float eff = 0.f;
    if (n < N_NODES) {
        float L = 0.f;
#pragma unroll
        for (int k = 0; k < KNBR; k++) L += nmask[n*KNBR + k];
        g_lens[n] = L;
        eff = (L > 0.f) ? L : 1.0f;
    }
    __shared__ float red[256];
    red[threadIdx.x] = eff;
    __syncthreads();
    for (int s = 128; s > 0; s >>= 1) {
        if (threadIdx.x < s) red[threadIdx.x] += red[threadIdx.x + s];
        __syncthreads();
    }
    if (threadIdx.x == 0) atomicAdd(&g_cnt, (double)red[0]);
}

// ---------------- K1: persistent e_lin GEMV (f32x2) ----------------
// tile = 128 edges; 512 threads; thread = 4 edges x 4 cols.
__global__ __launch_bounds__(512,1) void k1_edge(
    const float* __restrict__ nodef, const float* __restrict__ edgef,
    const int* __restrict__ nbr, const float* __restrict__ nmask,
    const float* __restrict__ W, const float* __restrict__ bE)
{
    extern __shared__ float smem[];
    ulonglong2* sWA = (ulonglong2*)smem;            // 16*97
    ulonglong2* sWB = sWA + 16*97;                  // 16*97
    float* sC   = (float*)(sWB + 16*97);            // 128*CST
    float* sSum = sC + 128*CST;                     // 64
    float* sSsq = sSum + 64;                        // 64
    __shared__ unsigned int s_tile;

    int t = threadIdx.x;
    for (int i = t; i < 16*96; i += 512) {
        int jq = i / 96, p = i - jq*96;
        int j0 = jq*4, c0 = 2*p;
        ulonglong2 a, b;
        a.x = pack2(W[c0*64+j0],   W[(c0+1)*64+j0]);
        a.y = pack2(W[c0*64+j0+1], W[(c0+1)*64+j0+1]);
        b.x = pack2(W[c0*64+j0+2], W[(c0+1)*64+j0+2]);
        b.y = pack2(W[c0*64+j0+3], W[(c0+1)*64+j0+3]);
        sWA[jq*97+p] = a; sWB[jq*97+p] = b;
    }
    if (t < 64) { sSum[t] = 0.f; sSsq[t] = 0.f; }

    int jg = t & 15, eg = t >> 4;
    int j0 = jg*4, e0 = eg*4;
    float4 bj = *(const float4*)&bE[j0];
    const ulonglong2* pA = &sWA[jg*97];
    const ulonglong2* pB = &sWB[jg*97];
    float pS[4] = {0,0,0,0}, pQ[4] = {0,0,0,0};

    const int NT = (NEDGE + 127) / 128;
    for (;;) {
        if (t == 0) s_tile = atomicAdd(&g_t1, 1u);
        __syncthreads();
        int tile = (int)s_tile;
        if (tile >= NT) break;
        int eb = tile * 128;

        for (int i = t; i < 2048; i += 512) {
            int le = i >> 4, c4 = (i & 15) << 2, e = eb + le;
            float4 v = {0,0,0,0};
            if (e < NEDGE) v = *(const float4*)&nodef[(e/KNBR)*64 + c4];
            *(float4*)&sC[le*CST + c4] = v;
        }
        for (int i = t; i < 2048; i += 512) {
            int le = i >> 4, c4 = (i & 15) << 2, e = eb + le;
            float4 v = {0,0,0,0};
            if (e < NEDGE) v = *(const float4*)&nodef[nbr[e]*64 + c4];
            *(float4*)&sC[le*CST + 64 + c4] = v;
        }
        for (int i = t; i < 2048; i += 512) {
            int le = i >> 4, c4 = (i & 15) << 2, e = eb + le;
            float4 v = {0,0,0,0};
            if (e < NEDGE) v = *(const float4*)&edgef[e*64 + c4];
            *(float4*)&sC[le*CST + 128 + c4] = v;
        }
        __syncthreads();

        ull acc[4][4];
#pragma unroll
        for (int a = 0; a < 4; a++) { acc[a][0]=0; acc[a][1]=0; acc[a][2]=0; acc[a][3]=0; }
        const float* cb = &sC[e0*CST];
#pragma unroll 4
        for (int c4 = 0, p = 0; c4 < 192; c4 += 4, p += 2) {
            ulonglong2 cv[4];
#pragma unroll
            for (int ee = 0; ee < 4; ee++) cv[ee] = *(const ulonglong2*)(cb + ee*CST + c4);
#pragma unroll
            for (int pp = 0; pp < 2; pp++) {
                ulonglong2 wa = pA[p+pp], wb = pB[p+pp];
#pragma unroll
                for (int ee = 0; ee < 4; ee++) {
                    ull c2 = pp ? cv[ee].y : cv[ee].x;
                    ffma2(acc[ee][0], c2, wa.x);
                    ffma2(acc[ee][1], c2, wa.y);
                    ffma2(acc[ee][2], c2, wb.x);
                    ffma2(acc[ee][3], c2, wb.y);
                }
            }
        }
#pragma unroll
        for (int ee = 0; ee < 4; ee++) {
            int e = eb + e0 + ee;
            if (e >= NEDGE) break;
            float2 u0 = unpack2(acc[ee][0]), u1 = unpack2(acc[ee][1]);
            float2 u2 = unpack2(acc[ee][2]), u3 = unpack2(acc[ee][3]);
            float4 o;
            o.x = u0.x+u0.y+bj.x; o.y = u1.x+u1.y+bj.y;
            o.z = u2.x+u2.y+bj.z; o.w = u3.x+u3.y+bj.w;
            *(float4*)&g_elin[e*64 + j0] = o;
            int n = e / KNBR, k = e - n*KNBR;
            float L = g_lens[n];
            float m = (L > 0.f) ? nmask[e] : (k == 0 ? 1.f : 0.f);
            pS[0] += o.x*m; pQ[0] += o.x*o.x*m;
            pS[1] += o.y*m; pQ[1] += o.y*o.y*m;
            pS[2] += o.z*m; pQ[2] += o.z*o.z*m;
            pS[3] += o.w*m; pQ[3] += o.w*o.w*m;
        }
    }
#pragma unroll
    for (int jj = 0; jj < 4; jj++) {
        pS[jj] += __shfl_down_sync(0xffffffffu, pS[jj], 16);
        pQ[jj] += __shfl_down_sync(0xffffffffu, pQ[jj], 16);
    }
    if ((t & 31) < 16) {
#pragma unroll
        for (int jj = 0; jj < 4; jj++) {
            atomicAdd(&sSum[j0+jj], pS[jj]);
            atomicAdd(&sSsq[j0+jj], pQ[jj]);
        }
    }
    __syncthreads();
    if (t < 64) {
        atomicAdd(&g_sumE[t], (double)sSum[t]);
        atomicAdd(&g_ssqE[t], (double)sSsq[t]);
    }
}

// ---------------- K_fin ----------------
__global__ void k_finalize(const float* __restrict__ gamma,
                           const float* __restrict__ beta, int which)
{
    int j = threadIdx.x;
    if (j >= 64) return;
    double cnt = (which == 2) ? (double)N_NODES : g_cnt;
    double s, q;
    if (which == 0)      { s = g_sumE[j]; q = g_ssqE[j]; }
    else if (which == 1) { s = g_sumP[j]; q = g_ssqP[j]; }
    else                 { s = g_sumO[j]; q = g_ssqO[j]; }
    double mean = s / cnt;
    double var  = q / cnt - mean * mean;
    float inv   = (float)(1.0 / sqrt(var + (double)EPSV));
    float sc    = gamma[j] * inv;
    g_coefs[which*128 + j]      = sc;
    g_coefs[which*128 + 64 + j] = beta[j] - (float)mean * sc;
}

__device__ __forceinline__ float w3(const float* W1, const float* Wv, int c, int j) {
    if (j < 64) return W1[((j>>4)*192 + c)*16 + (j & 15)];
    int jv = j - 64;
    return Wv[((jv>>4)*192 + c)*16 + (jv & 15)];
}

// ---------------- K3: persistent fused edge-update + attention + value -----
// tile = 8 nodes (96 edges); 512 threads; gemv thread = 6 edges x 4 cols.
__global__ __launch_bounds__(512,1) void k3_att(
    const float* __restrict__ nodef, const float* __restrict__ edgef,
    const int* __restrict__ nbr, const float* __restrict__ nmask,
    const float* __restrict__ W1, const float* __restrict__ b1,
    const float* __restrict__ W2, const float* __restrict__ b2,
    const float* __restrict__ Wv, const float* __restrict__ bv,
    float* __restrict__ out_edges)
{
    extern __shared__ float smem[];
    ulonglong2* sWA = (ulonglong2*)smem;      // 32*97
    ulonglong2* sWB = sWA + 32*97;            // 32*97
    float* sC    = (float*)(sWB + 32*97);     // 96*CST
    float* sV    = sC + 96*CST;               // 96*64
    float* sCoef = sV + 6144;                 // 128
    float* sB1   = sCoef + 128;               // 64
    float* sBV   = sB1 + 64;                  // 64
    float* sW2   = sBV + 64;                  // 64
    float* sLog  = sW2 + 64;                  // 384
    float* sAtt  = sLog + 384;                // 384
    float* sM    = sAtt + 384;                // 96
    float* sSum  = sM + 96;                   // 64
    float* sSsq  = sSum + 64;                 // 64
    __shared__ unsigned int s_tile;

    int t = threadIdx.x;
    for (int i = t; i < 32*96; i += 512) {
        int jq = i / 96, p = i - jq*96;
        int j0 = jq*4, c0 = 2*p;
        ulonglong2 a, b;
        a.x = pack2(w3(W1,Wv,c0,j0),   w3(W1,Wv,c0+1,j0));
        a.y = pack2(w3(W1,Wv,c0,j0+1), w3(W1,Wv,c0+1,j0+1));
        b.x = pack2(w3(W1,Wv,c0,j0+2), w3(W1,Wv,c0+1,j0+2));
        b.y = pack2(w3(W1,Wv,c0,j0+3), w3(W1,Wv,c0+1,j0+3));
        sWA[jq*97+p] = a; sWB[jq*97+p] = b;
    }
    if (t < 128) sCoef[t] = g_coefs[t];
    if (t < 64)  { sB1[t] = b1[t]; sBV[t] = bv[t]; sW2[t] = W2[t];
                   sSum[t] = 0.f; sSsq[t] = 0.f; }

    int jq = t & 31, eg = t >> 5;
    int j0 = jq*4, e0 = eg*6;
    const ulonglong2* pA = &sWA[jq*97];
    const ulonglong2* pB = &sWB[jq*97];
    int jq4 = t & 15, eg4 = t >> 4;
    float pS[4] = {0,0,0,0}, pQ[4] = {0,0,0,0};

    const int NT = N_NODES / 8;
    for (;;) {
        if (t == 0) s_tile = atomicAdd(&g_t3, 1u);
        __syncthreads();
        int tile = (int)s_tile;
        if (tile >= NT) break;
        int n0 = tile * 8, eb = n0 * KNBR;

        if (t < 96) {
            int e = eb + t, n = n0 + t/KNBR, k = t - (t/KNBR)*KNBR;
            float L = g_lens[n];
            sM[t] = (L > 0.f) ? nmask[e] : (k == 0 ? 1.f : 0.f);
        }
        for (int i = t; i < 3072; i += 512) {
            int le = i >> 5, c4 = (i & 31) << 2;
            int e = eb + le, n = n0 + le/KNBR;
            float4 v = (c4 < 64) ? *(const float4*)&nodef[n*64 + c4]
                                 : *(const float4*)&nodef[nbr[e]*64 + (c4-64)];
            *(float4*)&sC[le*CST + c4] = v;
        }
        __syncthreads();
        for (int i = t; i < 1536; i += 512) {
            int le = i >> 4, j = (i & 15) << 2;
            int e = eb + le;
            float m = sM[le];
            float4 el = *(const float4*)&g_elin[e*64 + j];
            float4 ef = *(const float4*)&edgef[e*64 + j];
            float4 sc = *(const float4*)&sCoef[j];
            float4 sh = *(const float4*)&sCoef[64 + j];
            float4 eu;
            eu.x = fsp(ef.x + (el.x*sc.x + sh.x)*m);
            eu.y = fsp(ef.y + (el.y*sc.y + sh.y)*m);
            eu.z = fsp(ef.z + (el.z*sc.z + sh.z)*m);
            eu.w = fsp(ef.w + (el.w*sc.w + sh.w)*m);
            *(float4*)&out_edges[e*64 + j] = eu;
            *(float4*)&sC[le*CST + 128 + j] = eu;
        }
        __syncthreads();

        ull acc[6][4];
#pragma unroll
        for (int a = 0; a < 6; a++) { acc[a][0]=0; acc[a][1]=0; acc[a][2]=0; acc[a][3]=0; }
        const float* cb = &sC[e0*CST];
#pragma unroll 2
        for (int c4 = 0, p = 0; c4 < 192; c4 += 4, p += 2) {
            ulonglong2 cv[6];
#pragma unroll
            for (int ee = 0; ee < 6; ee++) cv[ee] = *(const ulonglong2*)(cb + ee*CST + c4);
#pragma unroll
            for (int pp = 0; pp < 2; pp++) {
                ulonglong2 wa = pA[p+pp], wb = pB[p+pp];
#pragma unroll
                for (int ee = 0; ee < 6; ee++) {
                    ull c2 = pp ? cv[ee].y : cv[ee].x;
                    ffma2(acc[ee][0], c2, wa.x);
                    ffma2(acc[ee][1], c2, wa.y);
                    ffma2(acc[ee][2], c2, wb.x);
                    ffma2(acc[ee][3], c2, wb.y);
                }
            }
        }

        float lp[6];
        if (j0 < 64) {
            float4 b1v = *(const float4*)&sB1[j0];
            float4 w2v = *(const float4*)&sW2[j0];
#pragma unroll
            for (int ee = 0; ee < 6; ee++) {
                float2 u0 = unpack2(acc[ee][0]), u1 = unpack2(acc[ee][1]);
                float2 u2 = unpack2(acc[ee][2]), u3 = unpack2(acc[ee][3]);
                lp[ee] = fsp(u0.x+u0.y+b1v.x)*w2v.x
                       + fsp(u1.x+u1.y+b1v.y)*w2v.y
                       + fsp(u2.x+u2.y+b1v.z)*w2v.z
                       + fsp(u3.x+u3.y+b1v.w)*w2v.w;
            }
        } else {
            int jv = j0 - 64;
            float4 bvv = *(const float4*)&sBV[jv];
#pragma unroll
            for (int ee = 0; ee < 6; ee++) {
                float2 u0 = unpack2(acc[ee][0]), u1 = unpack2(acc[ee][1]);
                float2 u2 = unpack2(acc[ee][2]), u3 = unpack2(acc[ee][3]);
                float4 v;
                v.x = u0.x+u0.y+bvv.x; v.y = u1.x+u1.y+bvv.y;
                v.z = u2.x+u2.y+bvv.z; v.w = u3.x+u3.y+bvv.w;
                *(float4*)&sV[(e0+ee)*64 + jv] = v;
                lp[ee] = 0.f;
            }
        }
#pragma unroll
        for (int ee = 0; ee < 6; ee++) {
            float v = lp[ee];
            v += __shfl_xor_sync(0xffffffffu, v, 1);
            v += __shfl_xor_sync(0xffffffffu, v, 2);
            if (j0 < 64 && (jq & 3) == 0) sLog[(e0+ee)*4 + (jq >> 2)] = v;
        }
        __syncthreads();

        if (t < 32) {
            int ln = t >> 2, h = t & 3;
            float mx = -1e30f;
#pragma unroll
            for (int k = 0; k < KNBR; k++) {
                int le = ln*KNBR + k;
                if (sM[le] > 0.f) mx = fmaxf(mx, sLog[le*4 + h]);
            }
            float ex[KNBR]; float ss = 0.f;
#pragma unroll
            for (int k = 0; k < KNBR; k++) {
                int le = ln*KNBR + k;
                float v = (sM[le] > 0.f) ? expf(sLog[le*4 + h] - mx) : 0.f;
                ex[k] = v; ss += v;
            }
            float inv = 1.f / ss;
#pragma unroll
            for (int k = 0; k < KNBR; k++) sAtt[(ln*KNBR + k)*4 + h] = ex[k]*inv;
        }
        __syncthreads();

        int j = jq4*4, h4 = j >> 4;
#pragma unroll
        for (int r = 0; r < 3; r++) {
            int le = eg4 + 32*r;
            float a = sAtt[le*4 + h4], m = sM[le];
            float4 v = *(const float4*)&sV[le*64 + j];
            float4 pz; pz.x = a*v.x; pz.y = a*v.y; pz.z = a*v.z; pz.w = a*v.w;
            *(float4*)&g_elin[(eb+le)*64 + j] = pz;
            pS[0] += pz.x*m; pQ[0] += pz.x*pz.x*m;
            pS[1] += pz.y*m; pQ[1] += pz.y*pz.y*m;
            pS[2] += pz.z*m; pQ[2] += pz.z*pz.z*m;
            pS[3] += pz.w*m; pQ[3] += pz.w*pz.w*m;
        }
    }
#pragma unroll
    for (int jj = 0; jj < 4; jj++) {
        pS[jj] += __shfl_down_sync(0xffffffffu, pS[jj], 16);
        pQ[jj] += __shfl_down_sync(0xffffffffu, pQ[jj], 16);
    }
    if ((t & 31) < 16) {
        int jb = jq4*4;
#pragma unroll
        for (int jj = 0; jj < 4; jj++) {
            atomicAdd(&sSum[jb+jj], pS[jj]);
            atomicAdd(&sSsq[jb+jj], pQ[jj]);
        }
    }
    __syncthreads();
    if (t < 64) {
        atomicAdd(&g_sumP[t], (double)sSum[t]);
        atomicAdd(&g_ssqP[t], (double)sSsq[t]);
    }
}

// ---------------- K5: head_feats + pooled + out-BN stats ----------------
__global__ __launch_bounds__(256) void k5_pool(const float* __restrict__ nmask)
{
    int t = threadIdx.x;
    int j = t & 63, nl = t >> 6;
    int n0 = blockIdx.x * 64;
    float scP = g_coefs[128 + j], shP = g_coefs[192 + j];
    float psum = 0.f, pssq = 0.f;
    for (int i = 0; i < 16; i++) {
        int n = n0 + nl*16 + i;
        if (n >= N_NODES) break;
        float L = g_lens[n];
        float pooled = 0.f;
#pragma unroll
        for (int k = 0; k < KNBR; k++) {
            float m = (L > 0.f) ? nmask[n*KNBR + k] : (k == 0 ? 1.f : 0.f);
            float p = g_elin[(n*KNBR + k)*64 + j];
            pooled += fsp(p*scP + shP) * m;
        }
        g_pooled[n*64 + j] = pooled;
        psum += pooled; pssq += pooled*pooled;
    }
    __shared__ float red[256], red2[256];
    red[t] = psum; red2[t] = pssq;
    __syncthreads();
    if (nl == 0) {
        float s = red[j] + red[64+j] + red[128+j] + red[192+j];
        float q = red2[j] + red2[64+j] + red2[128+j] + red2[192+j];
        atomicAdd(&g_sumO[j], (double)s);
        atomicAdd(&g_ssqO[j], (double)q);
    }
}

// ---------------- K7 ----------------
__global__ void k7_out(const float* __restrict__ nodef, float* __restrict__ out_nodes)
{
    int i = blockIdx.x * 256 + threadIdx.x;
    if (i < N_NODES*64) {
        int j = i & 63;
        out_nodes[i] = nodef[i] + g_coefs[256 + j]*g_pooled[i] + g_coefs[320 + j];
    }
}

// ---------------- launch ----------------
extern "C" void kernel_launch(void* const* d_in, const int* in_sizes, int n_in,
                              void* d_out, int out_size)
{
    const float* nodef  = (const float*)d_in[0];
    const float* edgef  = (const float*)d_in[1];
    const int*   nbr    = (const int*)d_in[2];
    const float* nmask  = (const float*)d_in[3];
    const float* W_edge = (const float*)d_in[4];
    const float* b_edge = (const float*)d_in[5];
    const float* g_ebn  = (const float*)d_in[6];
    const float* b_ebn  = (const float*)d_in[7];
    const float* W1     = (const float*)d_in[8];
    const float* b1     = (const float*)d_in[9];
    const float* W2     = (const float*)d_in[10];
    const float* b2     = (const float*)d_in[11];
    const float* Wv     = (const float*)d_in[12];
    const float* bv     = (const float*)d_in[13];
    const float* g_abn  = (const float*)d_in[14];
    const float* b_abn  = (const float*)d_in[15];
    const float* g_obn  = (const float*)d_in[16];
    const float* b_obn  = (const float*)d_in[17];

    float* out_nodes = (float*)d_out;
    float* out_edges = out_nodes + (size_t)N_NODES * 64;

    const int smem1 = (16*97*4*2 + 128*CST + 128) * 4;                 // 150528
    const int smem3 = (32*97*4*2 + 96*CST + 6144 + 128 + 64*3
                       + 384 + 384 + 96 + 128) * 4;                    // 204416
    static int inited = 0;
    if (!inited) {
        cudaFuncSetAttribute(k1_edge, cudaFuncAttributeMaxDynamicSharedMemorySize, smem1);
        cudaFuncSetAttribute(k3_att,  cudaFuncAttributeMaxDynamicSharedMemorySize, smem3);
        inited = 1;
    }

    k_zero<<<1, 128>>>();
    k_lens<<<(N_NODES + 255)/256, 256>>>(nmask);
    k1_edge<<<NSM, 512, smem1>>>(nodef, edgef, nbr, nmask, W_edge, b_edge);
    k_finalize<<<1, 64>>>(g_ebn, b_ebn, 0);
    k3_att<<<NSM, 512, smem3>>>(nodef, edgef, nbr, nmask,
                                W1, b1, W2, b2, Wv, bv, out_edges);
    k_finalize<<<1, 64>>>(g_abn, b_abn, 1);
    k5_pool<<<(N_NODES + 63)/64, 256>>>(nmask);
    k_finalize<<<1, 64>>>(g_obn, b_obn, 2);
    k7_out<<<(N_NODES*64 + 255)/256, 256>>>(nodef, out_nodes);
}